// round 2
// baseline (speedup 1.0000x reference)
#include <cuda_runtime.h>

#define NN 4096
#define DD 128
#define BM 128
#define BN 128
#define BK 8

// scratch: e_ij matrix (64 MB), per-row data, global accumulators
__device__ float  g_E[(size_t)NN * NN];
__device__ float  g_p[NN], g_P[NN], g_yn[NN], g_xn[NN], g_Row[NN];
__device__ double g_acc[8];
// g_acc: [0]=Sp  [1]=SP  [2]=S_all  [3]=SlogE  [4]=SlogM  [5]=SsigPos  [6]=SsigNeg

// ---------------------------------------------------------------- zero
__global__ void kZero() {
    int t = threadIdx.x;
    for (int i = t; i < NN; i += 256) g_Row[i] = 0.f;
    if (t < 8) g_acc[t] = 0.0;
}

// ---------------------------------------------------------------- diag + norms
// one warp per row: ||y_i||^2, ||x_i||^2, y_i.x_i -> p_i, P_i
__global__ void kDiag(const float* __restrict__ X, const float* __restrict__ Y) {
    int warp = (blockIdx.x * blockDim.x + threadIdx.x) >> 5;
    int lane = threadIdx.x & 31;
    __shared__ double s_p[8], s_P[8];
    if (warp < NN) {
        const float4* x4 = (const float4*)(X + (size_t)warp * DD);
        const float4* y4 = (const float4*)(Y + (size_t)warp * DD);
        float4 xv = x4[lane];
        float4 yv = y4[lane];
        float xn = xv.x * xv.x + xv.y * xv.y + xv.z * xv.z + xv.w * xv.w;
        float yn = yv.x * yv.x + yv.y * yv.y + yv.z * yv.z + yv.w * yv.w;
        float cr = xv.x * yv.x + xv.y * yv.y + xv.z * yv.z + xv.w * yv.w;
        for (int o = 16; o > 0; o >>= 1) {
            xn += __shfl_xor_sync(0xffffffffu, xn, o);
            yn += __shfl_xor_sync(0xffffffffu, yn, o);
            cr += __shfl_xor_sync(0xffffffffu, cr, o);
        }
        if (lane == 0) {
            float sq = fmaxf(yn + xn - 2.f * cr, 0.f);
            float p  = 1.f / (1.f + sq);
            float P  = -__logf(1.f + sq);
            g_p[warp]  = p;
            g_P[warp]  = P;
            g_yn[warp] = yn;
            g_xn[warp] = xn;
            int w = threadIdx.x >> 5;
            s_p[w] = (double)p;
            s_P[w] = (double)P;
        }
    }
    __syncthreads();
    if (threadIdx.x == 0) {
        double sp = 0.0, sP = 0.0;
        for (int w = 0; w < 8; w++) { sp += s_p[w]; sP += s_P[w]; }
        atomicAdd(&g_acc[0], sp);
        atomicAdd(&g_acc[1], sP);
    }
}

// ---------------------------------------------------------------- main GEMM + stats
// 128x128 block tile, 8x8 thread tile, BK=8 double-buffered smem
__global__ __launch_bounds__(256, 2)
void kMain(const float* __restrict__ X, const float* __restrict__ Y) {
    __shared__ __align__(16) float As[2][BK][BM];
    __shared__ __align__(16) float Bs[2][BK][BN];
    __shared__ float ys[BM], xs[BN], ps[BM];
    __shared__ float red[3][8];

    const int m0 = blockIdx.y * BM;
    const int n0 = blockIdx.x * BN;
    const int t  = threadIdx.x;
    const int tx = t & 15;
    const int ty = t >> 4;

    if (t < 128) {
        ys[t] = g_yn[m0 + t];
        ps[t] = g_p[m0 + t];
        xs[t] = g_xn[n0 + t];
    }

    // global load mapping: each thread loads one float4 per tile per stage
    const int aRow = t >> 1;
    const int aCol = (t & 1) * 4;
    const float* Ag = Y + (size_t)(m0 + aRow) * DD + aCol;
    const float* Bg = X + (size_t)(n0 + aRow) * DD + aCol;

    float4 av = *(const float4*)Ag;
    float4 bv = *(const float4*)Bg;
    As[0][aCol + 0][aRow] = av.x; As[0][aCol + 1][aRow] = av.y;
    As[0][aCol + 2][aRow] = av.z; As[0][aCol + 3][aRow] = av.w;
    Bs[0][aCol + 0][aRow] = bv.x; Bs[0][aCol + 1][aRow] = bv.y;
    Bs[0][aCol + 2][aRow] = bv.z; Bs[0][aCol + 3][aRow] = bv.w;
    __syncthreads();

    float acc[8][8];
#pragma unroll
    for (int i = 0; i < 8; i++)
#pragma unroll
        for (int j = 0; j < 8; j++) acc[i][j] = 0.f;

    int buf = 0;
#pragma unroll 1
    for (int kk = 0; kk < DD / BK; kk++) {
        float4 an, bn;
        if (kk < DD / BK - 1) {
            an = *(const float4*)(Ag + (kk + 1) * BK);
            bn = *(const float4*)(Bg + (kk + 1) * BK);
        }
#pragma unroll
        for (int k = 0; k < BK; k++) {
            float a[8], b[8];
            *(float4*)&a[0] = *(const float4*)&As[buf][k][ty * 4];
            *(float4*)&a[4] = *(const float4*)&As[buf][k][64 + ty * 4];
            *(float4*)&b[0] = *(const float4*)&Bs[buf][k][tx * 4];
            *(float4*)&b[4] = *(const float4*)&Bs[buf][k][64 + tx * 4];
#pragma unroll
            for (int i = 0; i < 8; i++)
#pragma unroll
                for (int j = 0; j < 8; j++) acc[i][j] += a[i] * b[j];
        }
        if (kk < DD / BK - 1) {
            int nb = buf ^ 1;
            As[nb][aCol + 0][aRow] = an.x; As[nb][aCol + 1][aRow] = an.y;
            As[nb][aCol + 2][aRow] = an.z; As[nb][aCol + 3][aRow] = an.w;
            Bs[nb][aCol + 0][aRow] = bn.x; Bs[nb][aCol + 1][aRow] = bn.y;
            Bs[nb][aCol + 2][aRow] = bn.z; Bs[nb][aCol + 3][aRow] = bn.w;
            __syncthreads();
            buf = nb;
        }
    }

    // ------- epilogue: e = 1/(1+sq), accumulate stats, store e -------
    float se = 0.f, slE = 0.f, slM = 0.f;
#pragma unroll
    for (int i = 0; i < 8; i++) {
        int rm = (i < 4) ? (ty * 4 + i) : (64 + ty * 4 + i - 4);
        float yni = ys[rm];
        float pmi = ps[rm];
        float er = 0.f;
        float ev[8];
#pragma unroll
        for (int j = 0; j < 8; j++) {
            int rn = (j < 4) ? (tx * 4 + j) : (64 + tx * 4 + j - 4);
            float sq = fmaxf(yni + xs[rn] - 2.f * acc[i][j], 0.f);
            float op = 1.f + sq;
            float e  = __fdividef(1.f, op);
            ev[j] = e;
            se  += e;
            er  += e;
            slE -= __logf(op);
            slM += __logf(0.5f * (pmi + e));
        }
        float* dst = &g_E[(size_t)(m0 + rm) * NN + n0];
        *(float4*)(dst + tx * 4)      = make_float4(ev[0], ev[1], ev[2], ev[3]);
        *(float4*)(dst + 64 + tx * 4) = make_float4(ev[4], ev[5], ev[6], ev[7]);
        // half-warp (16 lanes share the same rows) reduce row sum
        for (int o = 1; o < 16; o <<= 1) er += __shfl_xor_sync(0xffffffffu, er, o);
        if ((t & 15) == 0) atomicAdd(&g_Row[m0 + rm], er);
    }

    // block reduction of the 3 scalars
    for (int o = 16; o > 0; o >>= 1) {
        se  += __shfl_xor_sync(0xffffffffu, se, o);
        slE += __shfl_xor_sync(0xffffffffu, slE, o);
        slM += __shfl_xor_sync(0xffffffffu, slM, o);
    }
    int w = t >> 5;
    if ((t & 31) == 0) { red[0][w] = se; red[1][w] = slE; red[2][w] = slM; }
    __syncthreads();
    if (t == 0) {
        double a0 = 0, a1 = 0, a2 = 0;
        for (int k = 0; k < 8; k++) { a0 += red[0][k]; a1 += red[1][k]; a2 += red[2][k]; }
        atomicAdd(&g_acc[2], a0);
        atomicAdd(&g_acc[3], a1);
        atomicAdd(&g_acc[4], a2);
    }
}

// ---------------------------------------------------------------- sigmoid pass
__global__ void kSig() {
    // derive global constant C = exp(lb0+lb1)
    double Sp    = g_acc[0];
    double S_all = g_acc[2];
    double S_N   = S_all - Sp;
    double S_M   = 0.5 * ((double)(NN - 1) * Sp + S_N);
    const double cnt = (double)NN * (double)(NN - 1);
    float C = (float)((S_M / cnt) * (S_N / cnt));

    size_t idx = ((size_t)blockIdx.x * blockDim.x + threadIdx.x) * 4;
    float sp = 0.f, sn = 0.f;
    if (idx < (size_t)NN * NN) {
        int m = (int)(idx >> 12);
        float pm = g_p[m];
        float4 ev = *(const float4*)&g_E[idx];
        float e;
        e = ev.x; { float u = 0.5f * pm * (pm + e), v = 0.5f * (pm + e) * e;
                    sp += __fdividef(u, u + C); sn += __fdividef(v, v + C); }
        e = ev.y; { float u = 0.5f * pm * (pm + e), v = 0.5f * (pm + e) * e;
                    sp += __fdividef(u, u + C); sn += __fdividef(v, v + C); }
        e = ev.z; { float u = 0.5f * pm * (pm + e), v = 0.5f * (pm + e) * e;
                    sp += __fdividef(u, u + C); sn += __fdividef(v, v + C); }
        e = ev.w; { float u = 0.5f * pm * (pm + e), v = 0.5f * (pm + e) * e;
                    sp += __fdividef(u, u + C); sn += __fdividef(v, v + C); }
    }
    for (int o = 16; o > 0; o >>= 1) {
        sp += __shfl_xor_sync(0xffffffffu, sp, o);
        sn += __shfl_xor_sync(0xffffffffu, sn, o);
    }
    __shared__ float rp[8], rn_[8];
    int w = threadIdx.x >> 5;
    if ((threadIdx.x & 31) == 0) { rp[w] = sp; rn_[w] = sn; }
    __syncthreads();
    if (threadIdx.x == 0) {
        double a = 0, b = 0;
        for (int k = 0; k < 8; k++) { a += rp[k]; b += rn_[k]; }
        atomicAdd(&g_acc[5], a);
        atomicAdd(&g_acc[6], b);
    }
}

// ---------------------------------------------------------------- final
__global__ void kFinal(float* __restrict__ out) {
    __shared__ double s_tp[256], s_d[256];
    int t = threadIdx.x;
    double Sp = g_acc[0], SP = g_acc[1], S_all = g_acc[2];
    double SlogE = g_acc[3], SlogM = g_acc[4], SsP = g_acc[5], SsN = g_acc[6];
    double S_N = S_all - Sp;
    const double cnt = (double)NN * (double)(NN - 1);
    double S_M = 0.5 * ((NN - 1.0) * Sp + S_N);
    double C   = (S_M / cnt) * (S_N / cnt);

    double tp = 0.0, dd = 0.0;
    for (int i = t; i < NN; i += 256) {
        double pm = (double)g_p[i];
        double R  = (double)g_Row[i] - pm;                  // off-diagonal row sum
        double w  = pm * 0.5 * ((NN - 1.0) * pm + R) / (NN - 1.0);
        tp += w / (w + C);
        dd += pm * pm / (pm * pm + C);
    }
    s_tp[t] = tp; s_d[t] = dd;
    __syncthreads();
    for (int o = 128; o > 0; o >>= 1) {
        if (t < o) { s_tp[t] += s_tp[t + o]; s_d[t] += s_d[t + o]; }
        __syncthreads();
    }
    if (t == 0) {
        double TP   = s_tp[0] / NN;
        double dsum = s_d[0];
        double lb0 = log(S_M / cnt), lb1 = log(S_N / cnt), L = lb0 + lb1;
        double meanP = SP / NN;
        double meanM = (SlogM - SP) / cnt;
        double meanN = (SlogE - SP) / cnt;
        double o0 = meanP + meanM - L;
        double o1 = meanM + meanN - L;
        double sigP = (SsP - dsum) / cnt;
        double sigN = (SsN - dsum) / cnt;
        double FP = sigN;
        out[0] = (float)o0;
        out[1] = (float)o1;
        out[2] = (float)sigP;
        out[3] = (float)sigN;
        out[4] = (float)((TP + 1.0 - FP) * 0.5);
        out[5] = (float)TP;
        out[6] = (float)(TP / (TP + FP));
        out[7] = (float)L;
        out[8] = (float)(2.0 - o0);   // gatt.mean()+grep.mean(); grep.mean()==2 exactly
    }
}

// ---------------------------------------------------------------- launch
extern "C" void kernel_launch(void* const* d_in, const int* in_sizes, int n_in,
                              void* d_out, int out_size) {
    const float* X = (const float*)d_in[0];   // z_x  (columns j)
    const float* Y = (const float*)d_in[1];   // z_y  (rows i)
    kZero<<<1, 256>>>();
    kDiag<<<NN / 8, 256>>>(X, Y);
    kMain<<<dim3(NN / BN, NN / BM), 256>>>(X, Y);
    kSig<<<(NN / 4) * (NN / 256), 256>>>();
    kFinal<<<1, 256>>>((float*)d_out);
}

// round 6
// speedup vs baseline: 2.0277x; 2.0277x over previous
#include <cuda_runtime.h>
#include <cuda_bf16.h>

#define NN 4096
#define DD 128
#define BM 128
#define BN 128
#define BK 8

// scratch: e_ij matrix (bf16, 32 MB), per-row data, global accumulators
__device__ __nv_bfloat16 g_E[(size_t)NN * NN];
__device__ float  g_p[NN], g_P[NN], g_yn[NN], g_xn[NN], g_Row[NN];
__device__ double g_acc[8];
// g_acc: [0]=Sp  [1]=SP  [2]=S_all  [3]=SlogE  [4]=SlogM  [5]=SsigPos  [6]=SsigNeg

// ---------------------------------------------------------------- zero
__global__ void kZero() {
    int t = threadIdx.x;
    for (int i = t; i < NN; i += 256) g_Row[i] = 0.f;
    if (t < 8) g_acc[t] = 0.0;
}

// ---------------------------------------------------------------- diag + norms
// one warp per row: ||y_i||^2, ||x_i||^2, y_i.x_i -> p_i, P_i
__global__ void kDiag(const float* __restrict__ X, const float* __restrict__ Y) {
    int warp = (blockIdx.x * blockDim.x + threadIdx.x) >> 5;
    int lane = threadIdx.x & 31;
    __shared__ double s_p[8], s_P[8];
    if (warp < NN) {
        const float4* x4 = (const float4*)(X + (size_t)warp * DD);
        const float4* y4 = (const float4*)(Y + (size_t)warp * DD);
        float4 xv = x4[lane];
        float4 yv = y4[lane];
        float xn = xv.x * xv.x + xv.y * xv.y + xv.z * xv.z + xv.w * xv.w;
        float yn = yv.x * yv.x + yv.y * yv.y + yv.z * yv.z + yv.w * yv.w;
        float cr = xv.x * yv.x + xv.y * yv.y + xv.z * yv.z + xv.w * yv.w;
        for (int o = 16; o > 0; o >>= 1) {
            xn += __shfl_xor_sync(0xffffffffu, xn, o);
            yn += __shfl_xor_sync(0xffffffffu, yn, o);
            cr += __shfl_xor_sync(0xffffffffu, cr, o);
        }
        if (lane == 0) {
            float sq = fmaxf(yn + xn - 2.f * cr, 0.f);
            float p  = 1.f / (1.f + sq);
            float P  = -__logf(1.f + sq);
            g_p[warp]  = p;
            g_P[warp]  = P;
            g_yn[warp] = yn;
            g_xn[warp] = xn;
            int w = threadIdx.x >> 5;
            s_p[w] = (double)p;
            s_P[w] = (double)P;
        }
    }
    __syncthreads();
    if (threadIdx.x == 0) {
        double sp = 0.0, sP = 0.0;
        for (int w = 0; w < 8; w++) { sp += s_p[w]; sP += s_P[w]; }
        atomicAdd(&g_acc[0], sp);
        atomicAdd(&g_acc[1], sP);
    }
}

// ---------------------------------------------------------------- main GEMM + stats
// 128x128 block tile, 8x8 thread tile, BK=8 double-buffered smem
__global__ __launch_bounds__(256, 2)
void kMain(const float* __restrict__ X, const float* __restrict__ Y) {
    __shared__ __align__(16) float As[2][BK][BM];
    __shared__ __align__(16) float Bs[2][BK][BN];
    __shared__ float ys[BM], xs[BN], ps[BM];
    __shared__ float red[3][8];

    const int m0 = blockIdx.y * BM;
    const int n0 = blockIdx.x * BN;
    const int t  = threadIdx.x;
    const int tx = t & 15;
    const int ty = t >> 4;

    if (t < 128) {
        ys[t] = g_yn[m0 + t];
        ps[t] = g_p[m0 + t];
        xs[t] = g_xn[n0 + t];
    }

    // global load mapping: each thread loads one float4 per tile per stage
    const int aRow = t >> 1;
    const int aCol = (t & 1) * 4;
    const float* Ag = Y + (size_t)(m0 + aRow) * DD + aCol;
    const float* Bg = X + (size_t)(n0 + aRow) * DD + aCol;

    float4 av = *(const float4*)Ag;
    float4 bv = *(const float4*)Bg;
    As[0][aCol + 0][aRow] = av.x; As[0][aCol + 1][aRow] = av.y;
    As[0][aCol + 2][aRow] = av.z; As[0][aCol + 3][aRow] = av.w;
    Bs[0][aCol + 0][aRow] = bv.x; Bs[0][aCol + 1][aRow] = bv.y;
    Bs[0][aCol + 2][aRow] = bv.z; Bs[0][aCol + 3][aRow] = bv.w;
    __syncthreads();

    float acc[8][8];
#pragma unroll
    for (int i = 0; i < 8; i++)
#pragma unroll
        for (int j = 0; j < 8; j++) acc[i][j] = 0.f;

    int buf = 0;
#pragma unroll 1
    for (int kk = 0; kk < DD / BK; kk++) {
        float4 an, bn;
        if (kk < DD / BK - 1) {
            an = *(const float4*)(Ag + (kk + 1) * BK);
            bn = *(const float4*)(Bg + (kk + 1) * BK);
        }
#pragma unroll
        for (int k = 0; k < BK; k++) {
            float a[8], b[8];
            *(float4*)&a[0] = *(const float4*)&As[buf][k][ty * 4];
            *(float4*)&a[4] = *(const float4*)&As[buf][k][64 + ty * 4];
            *(float4*)&b[0] = *(const float4*)&Bs[buf][k][tx * 4];
            *(float4*)&b[4] = *(const float4*)&Bs[buf][k][64 + tx * 4];
#pragma unroll
            for (int i = 0; i < 8; i++)
#pragma unroll
                for (int j = 0; j < 8; j++) acc[i][j] += a[i] * b[j];
        }
        if (kk < DD / BK - 1) {
            int nb = buf ^ 1;
            As[nb][aCol + 0][aRow] = an.x; As[nb][aCol + 1][aRow] = an.y;
            As[nb][aCol + 2][aRow] = an.z; As[nb][aCol + 3][aRow] = an.w;
            Bs[nb][aCol + 0][aRow] = bn.x; Bs[nb][aCol + 1][aRow] = bn.y;
            Bs[nb][aCol + 2][aRow] = bn.z; Bs[nb][aCol + 3][aRow] = bn.w;
            __syncthreads();
            buf = nb;
        }
    }

    // ------- epilogue: e = 1/(1+sq), accumulate stats, store e (bf16) -------
    float se = 0.f, slE = 0.f, slM = 0.f;
#pragma unroll
    for (int i = 0; i < 8; i++) {
        int rm = (i < 4) ? (ty * 4 + i) : (64 + ty * 4 + i - 4);
        float yni = ys[rm];
        float pmi = ps[rm];
        float er = 0.f;
        float ev[8];
#pragma unroll
        for (int j = 0; j < 8; j++) {
            int rn = (j < 4) ? (tx * 4 + j) : (64 + tx * 4 + j - 4);
            float sq = fmaxf(yni + xs[rn] - 2.f * acc[i][j], 0.f);
            float op = 1.f + sq;
            float e  = __fdividef(1.f, op);
            ev[j] = e;
            se  += e;
            er  += e;
            slE -= __logf(op);
            slM += __logf(0.5f * (pmi + e));
        }
        // pack to bf16 and store (8 bytes per 4-element group)
        __nv_bfloat16* dst = &g_E[(size_t)(m0 + rm) * NN + n0];
        __nv_bfloat162 p01 = __float22bfloat162_rn(make_float2(ev[0], ev[1]));
        __nv_bfloat162 p23 = __float22bfloat162_rn(make_float2(ev[2], ev[3]));
        __nv_bfloat162 p45 = __float22bfloat162_rn(make_float2(ev[4], ev[5]));
        __nv_bfloat162 p67 = __float22bfloat162_rn(make_float2(ev[6], ev[7]));
        uint2 u0 = make_uint2(*(unsigned*)&p01, *(unsigned*)&p23);
        uint2 u1 = make_uint2(*(unsigned*)&p45, *(unsigned*)&p67);
        *(uint2*)(dst + tx * 4)      = u0;
        *(uint2*)(dst + 64 + tx * 4) = u1;
        // half-warp (16 lanes share the same rows) reduce row sum
        for (int o = 1; o < 16; o <<= 1) er += __shfl_xor_sync(0xffffffffu, er, o);
        if ((t & 15) == 0) atomicAdd(&g_Row[m0 + rm], er);
    }

    // block reduction of the 3 scalars
    for (int o = 16; o > 0; o >>= 1) {
        se  += __shfl_xor_sync(0xffffffffu, se, o);
        slE += __shfl_xor_sync(0xffffffffu, slE, o);
        slM += __shfl_xor_sync(0xffffffffu, slM, o);
    }
    int w = t >> 5;
    if ((t & 31) == 0) { red[0][w] = se; red[1][w] = slE; red[2][w] = slM; }
    __syncthreads();
    if (t == 0) {
        double a0 = 0, a1 = 0, a2 = 0;
        for (int k = 0; k < 8; k++) { a0 += red[0][k]; a1 += red[1][k]; a2 += red[2][k]; }
        atomicAdd(&g_acc[2], a0);
        atomicAdd(&g_acc[3], a1);
        atomicAdd(&g_acc[4], a2);
    }
}

// ---------------------------------------------------------------- sigmoid pass
// grid-stride, deep MLP, few blocks -> few atomics, DRAM-bandwidth bound
#define SIG_BLOCKS 1184
__global__ __launch_bounds__(256, 8) void kSig() {
    // derive global constant C = exp(lb0+lb1)
    double Sp    = g_acc[0];
    double S_all = g_acc[2];
    double S_N   = S_all - Sp;
    double S_M   = 0.5 * ((double)(NN - 1) * Sp + S_N);
    const double cnt = (double)NN * (double)(NN - 1);
    float C = (float)((S_M / cnt) * (S_N / cnt));

    const size_t nvec   = (size_t)NN * NN / 8;           // 2,097,152 uint4s (8 bf16 each)
    const size_t stride = (size_t)SIG_BLOCKS * 256;
    size_t tid = (size_t)blockIdx.x * 256 + threadIdx.x;

    float sp = 0.f, sn = 0.f;
    for (size_t i = tid; i < nvec; i += stride) {
        int m = (int)((i * 8) >> 12);                    // row index (4096 cols/row)
        float pm = __ldg(&g_p[m]);
        uint4 raw = __ldg((const uint4*)&g_E[i * 8]);
        float2 f;
        float e;
#define SIG_TERM(E) { e = (E); float u = 0.5f * pm * (pm + e), v = 0.5f * (pm + e) * e; \
                      sp += __fdividef(u, u + C); sn += __fdividef(v, v + C); }
        f = __bfloat1622float2(*(__nv_bfloat162*)&raw.x); SIG_TERM(f.x); SIG_TERM(f.y);
        f = __bfloat1622float2(*(__nv_bfloat162*)&raw.y); SIG_TERM(f.x); SIG_TERM(f.y);
        f = __bfloat1622float2(*(__nv_bfloat162*)&raw.z); SIG_TERM(f.x); SIG_TERM(f.y);
        f = __bfloat1622float2(*(__nv_bfloat162*)&raw.w); SIG_TERM(f.x); SIG_TERM(f.y);
#undef SIG_TERM
    }
    for (int o = 16; o > 0; o >>= 1) {
        sp += __shfl_xor_sync(0xffffffffu, sp, o);
        sn += __shfl_xor_sync(0xffffffffu, sn, o);
    }
    __shared__ double rp[8], rn_[8];
    int w = threadIdx.x >> 5;
    if ((threadIdx.x & 31) == 0) { rp[w] = (double)sp; rn_[w] = (double)sn; }
    __syncthreads();
    if (threadIdx.x == 0) {
        double a = 0, b = 0;
        for (int k = 0; k < 8; k++) { a += rp[k]; b += rn_[k]; }
        atomicAdd(&g_acc[5], a);
        atomicAdd(&g_acc[6], b);
    }
}

// ---------------------------------------------------------------- final
__global__ void kFinal(float* __restrict__ out) {
    __shared__ double s_tp[256], s_d[256];
    int t = threadIdx.x;
    double Sp = g_acc[0], SP = g_acc[1], S_all = g_acc[2];
    double SlogE = g_acc[3], SlogM = g_acc[4], SsP = g_acc[5], SsN = g_acc[6];
    double S_N = S_all - Sp;
    const double cnt = (double)NN * (double)(NN - 1);
    double S_M = 0.5 * ((NN - 1.0) * Sp + S_N);
    double C   = (S_M / cnt) * (S_N / cnt);

    double tp = 0.0, dd = 0.0;
    for (int i = t; i < NN; i += 256) {
        double pm = (double)g_p[i];
        double R  = (double)g_Row[i] - pm;                  // off-diagonal row sum
        double w  = pm * 0.5 * ((NN - 1.0) * pm + R) / (NN - 1.0);
        tp += w / (w + C);
        dd += pm * pm / (pm * pm + C);
    }
    s_tp[t] = tp; s_d[t] = dd;
    __syncthreads();
    for (int o = 128; o > 0; o >>= 1) {
        if (t < o) { s_tp[t] += s_tp[t + o]; s_d[t] += s_d[t + o]; }
        __syncthreads();
    }
    if (t == 0) {
        double TP   = s_tp[0] / NN;
        double dsum = s_d[0];
        double lb0 = log(S_M / cnt), lb1 = log(S_N / cnt), L = lb0 + lb1;
        double meanP = SP / NN;
        double meanM = (SlogM - SP) / cnt;
        double meanN = (SlogE - SP) / cnt;
        double o0 = meanP + meanM - L;
        double o1 = meanM + meanN - L;
        double sigP = (SsP - dsum) / cnt;
        double sigN = (SsN - dsum) / cnt;
        double FP = sigN;
        out[0] = (float)o0;
        out[1] = (float)o1;
        out[2] = (float)sigP;
        out[3] = (float)sigN;
        out[4] = (float)((TP + 1.0 - FP) * 0.5);
        out[5] = (float)TP;
        out[6] = (float)(TP / (TP + FP));
        out[7] = (float)L;
        out[8] = (float)(2.0 - o0);   // gatt.mean()+grep.mean(); grep.mean()==2 exactly
    }
}

// ---------------------------------------------------------------- launch
extern "C" void kernel_launch(void* const* d_in, const int* in_sizes, int n_in,
                              void* d_out, int out_size) {
    const float* X = (const float*)d_in[0];   // z_x  (columns j)
    const float* Y = (const float*)d_in[1];   // z_y  (rows i)
    kZero<<<1, 256>>>();
    kDiag<<<NN / 8, 256>>>(X, Y);
    kMain<<<dim3(NN / BN, NN / BM), 256>>>(X, Y);
    kSig<<<SIG_BLOCKS, 256>>>();
    kFinal<<<1, 256>>>((float*)d_out);
}